// round 5
// baseline (speedup 1.0000x reference)
#include <cuda_runtime.h>
#include <cuda_fp16.h>
#include <mma.h>
#include <cstdint>

using namespace nvcuda;

// Problem constants: 50000 nodes, 1.6M edges, 128->64->32->1
#define MAXN 50000
#define MAXE 1600000
#define C1 64
#define C2 32
#define NBLK 148
#define NTHR 512

// Scratch (static __device__ — no allocation allowed)
__device__ float g_dinv[MAXN];
__device__ int   g_deg[MAXN];
__device__ int   g_rowptr[MAXN];
__device__ int   g_cursor[MAXN];
__device__ int   g_srcs[MAXE];
__device__ int   g_blocksum[256];
__device__ __align__(16) __half g_g1h[(size_t)MAXN * C1];
__device__ __align__(16) __half g_g2h[(size_t)MAXN * C2];
__device__ int   g_is64;

// Grid barrier state (self-resetting: cnt returns to 0 after each barrier)
__device__ unsigned int g_bar_cnt = 0;
__device__ unsigned int g_bar_gen = 0;

__device__ __forceinline__ void grid_barrier() {
    __syncthreads();
    if (threadIdx.x == 0) {
        volatile unsigned int* genp = &g_bar_gen;
        unsigned int gen = *genp;
        __threadfence();
        if (atomicAdd(&g_bar_cnt, 1u) == (unsigned)NBLK - 1u) {
            g_bar_cnt = 0;
            __threadfence();
            atomicAdd(&g_bar_gen, 1u);
        } else {
            while (*genp == gen) { }
        }
        __threadfence();
    }
    __syncthreads();
}

__device__ __forceinline__ int load_idx(const void* ei, int is64, long long pos) {
    if (is64) return (int)((const long long*)ei)[pos];
    return ((const int*)ei)[pos];
}

__device__ __forceinline__ void acc_h8(float* acc, uint4 v, float d) {
    __half2 p0 = *reinterpret_cast<__half2*>(&v.x);
    __half2 p1 = *reinterpret_cast<__half2*>(&v.y);
    __half2 p2 = *reinterpret_cast<__half2*>(&v.z);
    __half2 p3 = *reinterpret_cast<__half2*>(&v.w);
    float2 f0 = __half22float2(p0);
    float2 f1 = __half22float2(p1);
    float2 f2 = __half22float2(p2);
    float2 f3 = __half22float2(p3);
    acc[0] = fmaf(d, f0.x, acc[0]); acc[1] = fmaf(d, f0.y, acc[1]);
    acc[2] = fmaf(d, f1.x, acc[2]); acc[3] = fmaf(d, f1.y, acc[3]);
    acc[4] = fmaf(d, f2.x, acc[4]); acc[5] = fmaf(d, f2.y, acc[5]);
    acc[6] = fmaf(d, f3.x, acc[6]); acc[7] = fmaf(d, f3.y, acc[7]);
}

__device__ __forceinline__ void unpack_h8(float* gs, uint4 gv) {
    __half2 p0 = *reinterpret_cast<__half2*>(&gv.x);
    __half2 p1 = *reinterpret_cast<__half2*>(&gv.y);
    __half2 p2 = *reinterpret_cast<__half2*>(&gv.z);
    __half2 p3 = *reinterpret_cast<__half2*>(&gv.w);
    float2 f0 = __half22float2(p0), f1 = __half22float2(p1);
    float2 f2 = __half22float2(p2), f3 = __half22float2(p3);
    gs[0] = f0.x; gs[1] = f0.y; gs[2] = f1.x; gs[3] = f1.y;
    gs[4] = f2.x; gs[5] = f2.y; gs[6] = f3.x; gs[7] = f3.y;
}

#define HS 68   // padded smem row stride (floats)

__global__ __launch_bounds__(NTHR, 1) void gcn_kernel(
    const float* __restrict__ X, const void* __restrict__ ei, int E,
    const float* __restrict__ W1, const float* __restrict__ b1,
    const float* __restrict__ W2, const float* __restrict__ b2,
    const float* __restrict__ Wh, const float* __restrict__ bh,
    float* __restrict__ out, int nodes)
{
    __shared__ __align__(16) char buf[49152];
    int tid = threadIdx.x;
    int gid = blockIdx.x * NTHR + tid;
    const int stride = NBLK * NTHR;   // 75776

    // ===== P0: zero degree counters + dtype sniff ==========================
    for (int i = gid; i < nodes; i += stride) g_deg[i] = 0;
    if (blockIdx.x == 0 && tid == 0) {
        const unsigned int* p = (const unsigned int*)ei;
        int is64 = 1;
        #pragma unroll
        for (int k = 0; k < 32; k++)
            if (p[2 * k + 1] != 0u) { is64 = 0; break; }
        g_is64 = is64;
    }
    grid_barrier();

    int is64 = g_is64;

    // ===== P1: degree histogram + tensor-core GEMM1 ========================
    for (int e = gid; e < E; e += stride) {
        int dst = load_idx(ei, is64, (long long)E + e);
        atomicAdd(&g_deg[dst], 1);
    }
    {
        __half* Xh  = reinterpret_cast<__half*>(buf);           // [128][128] 32KB
        __half* W1s = reinterpret_cast<__half*>(buf + 32768);   // [128][64]  16KB
        float*  Cs  = reinterpret_cast<float*>(buf);            // overlays Xh

        for (int i = tid; i < 128 * C1; i += NTHR)
            W1s[i] = __float2half(W1[i]);
        __syncthreads();

        int tiles = (nodes + 127) >> 7;
        int warp = tid >> 5;
        for (int t = blockIdx.x; t < tiles; t += NBLK) {
            int rowBase = t << 7;
            // load X tile (4096 float4), fp32->fp16, pad OOB
            for (int u = tid; u < 4096; u += NTHR) {
                int row = u >> 5;
                int k4  = u & 31;
                float4 v = (rowBase + row < nodes)
                    ? reinterpret_cast<const float4*>(X)[(size_t)(rowBase + row) * 32 + k4]
                    : make_float4(0.f, 0.f, 0.f, 0.f);
                __half2 h0 = __floats2half2_rn(v.x, v.y);
                __half2 h1 = __floats2half2_rn(v.z, v.w);
                uint2 o;
                o.x = *reinterpret_cast<unsigned int*>(&h0);
                o.y = *reinterpret_cast<unsigned int*>(&h1);
                *reinterpret_cast<uint2*>(&Xh[row * 128 + k4 * 4]) = o;
            }
            __syncthreads();

            wmma::fragment<wmma::accumulator, 16, 16, 16, float> c[4];
            if (warp < 8) {
                #pragma unroll
                for (int n = 0; n < 4; n++) wmma::fill_fragment(c[n], 0.0f);
                #pragma unroll
                for (int k0 = 0; k0 < 8; k0++) {
                    wmma::fragment<wmma::matrix_a, 16, 16, 16, __half, wmma::row_major> a;
                    wmma::load_matrix_sync(a, Xh + warp * 16 * 128 + k0 * 16, 128);
                    #pragma unroll
                    for (int n = 0; n < 4; n++) {
                        wmma::fragment<wmma::matrix_b, 16, 16, 16, __half, wmma::row_major> b;
                        wmma::load_matrix_sync(b, W1s + k0 * 16 * 64 + n * 16, 64);
                        wmma::mma_sync(c[n], a, b, c[n]);
                    }
                }
            }
            __syncthreads();    // done reading Xh
            if (warp < 8) {
                #pragma unroll
                for (int n = 0; n < 4; n++)
                    wmma::store_matrix_sync(Cs + warp * 16 * 64 + n * 16, c[n], 64,
                                            wmma::mem_row_major);
            }
            __syncthreads();

            // write fp16 rows: 1024 uint4
            for (int u = tid; u < 1024; u += NTHR) {
                int row = u >> 3;
                int c4  = u & 7;
                if (rowBase + row >= nodes) continue;
                const float* src = &Cs[row * 64 + c4 * 8];
                __half2 h0 = __floats2half2_rn(src[0], src[1]);
                __half2 h1 = __floats2half2_rn(src[2], src[3]);
                __half2 h2 = __floats2half2_rn(src[4], src[5]);
                __half2 h3 = __floats2half2_rn(src[6], src[7]);
                uint4 o;
                o.x = *reinterpret_cast<unsigned int*>(&h0);
                o.y = *reinterpret_cast<unsigned int*>(&h1);
                o.z = *reinterpret_cast<unsigned int*>(&h2);
                o.w = *reinterpret_cast<unsigned int*>(&h3);
                reinterpret_cast<uint4*>(g_g1h)[(size_t)(rowBase + row) * 8 + c4] = o;
            }
            __syncthreads();    // before next iter overwrites Xh/Cs
        }
    }
    grid_barrier();

    // ===== P2a: per-block local scan of degree chunk =======================
    int chunk = (nodes + NBLK - 1) / NBLK;        // 338
    int i0 = blockIdx.x * chunk;
    int myi = i0 + tid;
    int myDeg = 0;
    {
        int* s = reinterpret_cast<int*>(buf);
        int v = 0;
        if (tid < chunk && myi < nodes) v = __ldcg(&g_deg[myi]);
        myDeg = v;
        s[tid] = v;
        __syncthreads();
        #pragma unroll
        for (int o = 1; o < NTHR; o <<= 1) {
            int t2 = (tid >= o) ? s[tid - o] : 0;
            __syncthreads();
            s[tid] += t2;
            __syncthreads();
        }
        if (tid < chunk && myi < nodes) g_rowptr[myi] = s[tid] - v;  // local excl
        if (tid == NTHR - 1) g_blocksum[blockIdx.x] = s[NTHR - 1];
    }
    grid_barrier();

    // ===== P2b: block-offset scan + finalize rowptr/cursor/dinv ============
    {
        int* s = reinterpret_cast<int*>(buf);
        int v = (tid < NBLK) ? __ldcg(&g_blocksum[tid]) : 0;
        s[tid] = v;
        __syncthreads();
        #pragma unroll
        for (int o = 1; o < NTHR; o <<= 1) {
            int t2 = (tid >= o) ? s[tid - o] : 0;
            __syncthreads();
            s[tid] += t2;
            __syncthreads();
        }
        if (tid < chunk && myi < nodes) {
            int off = (blockIdx.x > 0) ? s[blockIdx.x - 1] : 0;
            int r = g_rowptr[myi] + off;
            g_rowptr[myi] = r;
            g_cursor[myi] = r;
            g_dinv[myi] = rsqrtf((float)myDeg + 1.0f);
        }
    }
    grid_barrier();

    // ===== P3: counting-sort edges by dst ==================================
    for (int e = gid; e < E; e += stride) {
        int src = load_idx(ei, is64, e);
        int dst = load_idx(ei, is64, (long long)E + e);
        int pos = atomicAdd(&g_cursor[dst], 1);
        g_srcs[pos] = src;
    }
    grid_barrier();

    // ===== P4: gather1 + relu + GEMM2 ======================================
    {
        float* h_s = reinterpret_cast<float*>(buf);             // 64*HS floats
        float* W2s = h_s + 64 * HS;                             // 2048 floats
        float* b1s = W2s + C1 * C2;                             // 64 floats
        for (int i = tid; i < C1 * C2; i += NTHR) W2s[i] = W2[i];
        if (tid < C1) b1s[tid] = b1[tid];
        __syncthreads();

        int nl = tid >> 3;
        int c  = tid & 7;
        int tiles = (nodes + 63) >> 6;
        const uint4* G = reinterpret_cast<const uint4*>(g_g1h);

        for (int t = blockIdx.x; t < tiles; t += NBLK) {
            int node = (t << 6) + nl;
            int valid = (node < nodes);

            float acc[8];
            #pragma unroll
            for (int j = 0; j < 8; j++) acc[j] = 0.0f;

            if (valid) {
                int deg = g_deg[node];
                int base = g_rowptr[node];
                int i = 0;
                for (; i + 4 <= deg; i += 4) {
                    int s0 = g_srcs[base + i + 0];
                    int s1 = g_srcs[base + i + 1];
                    int s2 = g_srcs[base + i + 2];
                    int s3 = g_srcs[base + i + 3];
                    float d0 = g_dinv[s0], d1 = g_dinv[s1];
                    float d2 = g_dinv[s2], d3 = g_dinv[s3];
                    uint4 v0 = G[s0 * 8 + c];
                    uint4 v1 = G[s1 * 8 + c];
                    uint4 v2 = G[s2 * 8 + c];
                    uint4 v3 = G[s3 * 8 + c];
                    acc_h8(acc, v0, d0);
                    acc_h8(acc, v1, d1);
                    acc_h8(acc, v2, d2);
                    acc_h8(acc, v3, d3);
                }
                for (; i < deg; i++) {
                    int s = g_srcs[base + i];
                    acc_h8(acc, G[s * 8 + c], g_dinv[s]);
                }
                float d = g_dinv[node];
                float gs[8];
                unpack_h8(gs, G[node * 8 + c]);
                float* hp = &h_s[nl * HS + c * 8];
                #pragma unroll
                for (int j = 0; j < 8; j++)
                    hp[j] = fmaxf(fmaf(d, fmaf(d, gs[j], acc[j]), b1s[c * 8 + j]), 0.0f);
            }
            __syncthreads();

            if (valid) {
                float o0 = 0.f, o1 = 0.f, o2 = 0.f, o3 = 0.f;
                const float* hr = &h_s[nl * HS];
                #pragma unroll 8
                for (int k = 0; k < C1; k++) {
                    float hk = hr[k];
                    const float* w = &W2s[k * C2 + c * 4];
                    o0 = fmaf(hk, w[0], o0);
                    o1 = fmaf(hk, w[1], o1);
                    o2 = fmaf(hk, w[2], o2);
                    o3 = fmaf(hk, w[3], o3);
                }
                __half2 h0 = __floats2half2_rn(o0, o1);
                __half2 h1 = __floats2half2_rn(o2, o3);
                uint2 o;
                o.x = *reinterpret_cast<unsigned int*>(&h0);
                o.y = *reinterpret_cast<unsigned int*>(&h1);
                reinterpret_cast<uint2*>(g_g2h)[(size_t)node * 8 + c] = o;
            }
            __syncthreads();
        }
    }
    grid_barrier();

    // ===== P5: gather2 + head ==============================================
    {
        float* b2s = reinterpret_cast<float*>(buf);
        float* Whs = b2s + C2;
        if (tid < C2) { b2s[tid] = b2[tid]; Whs[tid] = Wh[tid]; }
        __syncthreads();
        float bhv = bh[0];

        int nl = tid >> 2;
        int c  = tid & 3;
        int tiles = (nodes + 127) >> 7;
        const uint4* G = reinterpret_cast<const uint4*>(g_g2h);

        for (int t = blockIdx.x; t < tiles; t += NBLK) {
            int node = (t << 7) + nl;
            int valid = (node < nodes);

            float acc[8];
            #pragma unroll
            for (int j = 0; j < 8; j++) acc[j] = 0.0f;
            float p = 0.0f;

            if (valid) {
                int deg = g_deg[node];
                int base = g_rowptr[node];
                int i = 0;
                for (; i + 4 <= deg; i += 4) {
                    int s0 = g_srcs[base + i + 0];
                    int s1 = g_srcs[base + i + 1];
                    int s2 = g_srcs[base + i + 2];
                    int s3 = g_srcs[base + i + 3];
                    float d0 = g_dinv[s0], d1 = g_dinv[s1];
                    float d2 = g_dinv[s2], d3 = g_dinv[s3];
                    uint4 v0 = G[s0 * 4 + c];
                    uint4 v1 = G[s1 * 4 + c];
                    uint4 v2 = G[s2 * 4 + c];
                    uint4 v3 = G[s3 * 4 + c];
                    acc_h8(acc, v0, d0);
                    acc_h8(acc, v1, d1);
                    acc_h8(acc, v2, d2);
                    acc_h8(acc, v3, d3);
                }
                for (; i < deg; i++) {
                    int s = g_srcs[base + i];
                    acc_h8(acc, G[s * 4 + c], g_dinv[s]);
                }
                float d = g_dinv[node];
                float gs[8];
                unpack_h8(gs, G[node * 4 + c]);
                #pragma unroll
                for (int j = 0; j < 8; j++) {
                    int ch = c * 8 + j;
                    float v = fmaf(d, fmaf(d, gs[j], acc[j]), b2s[ch]);
                    p = fmaf(fmaxf(v, 0.0f), Whs[ch], p);
                }
            }
            p += __shfl_xor_sync(0xffffffffu, p, 1);
            p += __shfl_xor_sync(0xffffffffu, p, 2);
            if (valid && c == 0) out[node] = p + bhv;
        }
    }
}

// ---------------------------------------------------------------------------
extern "C" void kernel_launch(void* const* d_in, const int* in_sizes, int n_in,
                              void* d_out, int out_size)
{
    const float* x  = (const float*)d_in[0];
    const void*  ei = d_in[1];
    const float* W1 = (const float*)d_in[2];
    const float* b1 = (const float*)d_in[3];
    const float* W2 = (const float*)d_in[4];
    const float* b2 = (const float*)d_in[5];
    const float* Wh = (const float*)d_in[6];
    const float* bh = (const float*)d_in[7];
    float* out = (float*)d_out;

    int nodes = in_sizes[0] / 128;
    int E = in_sizes[1] / 2;

    gcn_kernel<<<NBLK, NTHR>>>(x, ei, E, W1, b1, W2, b2, Wh, bh, out, nodes);
}